// round 1
// baseline (speedup 1.0000x reference)
#include <cuda_runtime.h>
#include <cstdint>

// Problem constants
#define Bc   16
#define Nn_  128
#define Mm   1024
#define DN_  512
#define DE_  256
#define WN_  128
#define WE_  128
#define Pp   512
#define HID_ 256

// ---------------- scratch (static device globals; no allocation) -------------
__device__ float d_X  [(size_t)Bc*Nn_*DN_];       // masked node feats
__device__ float d_T2 [(size_t)Bc*Nn_*DN_];       // A @ X
__device__ float d_h  [(size_t)Bc*Nn_*WN_];       // relu(T2 @ Wn)
__device__ float d_Xp [(size_t)Bc*Nn_*WN_];       // X @ Wn2
__device__ float d_Eg [(size_t)Bc*Mm*DE_];        // gathered+masked edge feats
__device__ float d_T1 [(size_t)Bc*Mm*DE_];        // L @ Eg
__device__ float d_g  [(size_t)Bc*Mm*WE_];        // relu(T1 @ We)
__device__ float d_agg[(size_t)Bc*Nn_*WE_];       // scatter-add of g by src
__device__ float d_efp[(size_t)Bc*Pp*DE_];        // edge feats at pairs
__device__ float d_ci [(size_t)Bc*Pp*512];        // classifier input
__device__ float d_hid[(size_t)3*Bc*Pp*HID_];     // MLP hidden (lr, cr, mr)

// ---------------- f32x2 helpers ----------------------------------------------
__device__ __forceinline__ unsigned long long pk2(float lo, float hi) {
    unsigned long long r;
    asm("mov.b64 %0, {%1,%2};" : "=l"(r) : "f"(lo), "f"(hi));
    return r;
}
__device__ __forceinline__ void up2(unsigned long long v, float& lo, float& hi) {
    asm("mov.b64 {%0,%1}, %2;" : "=f"(lo), "=f"(hi) : "l"(v));
}
__device__ __forceinline__ void ffma2(unsigned long long& acc, unsigned long long a,
                                      unsigned long long b) {
    asm("fma.rn.f32x2 %0, %1, %2, %3;" : "=l"(acc) : "l"(a), "l"(b), "l"(acc));
}

// ---------------- K1: X = nf*nmask ; T2 = A @ X  (sparse, per-row) -----------
__global__ void k_ax(const float* __restrict__ nf, const float* __restrict__ adj,
                     const int* __restrict__ num_obj) {
    int b = blockIdx.y, i = blockIdx.x, t = threadIdx.x;   // 128 threads
    int no = num_obj[b];
    float* Xrow = d_X  + ((size_t)b*Nn_ + i)*DN_;
    float* Trow = d_T2 + ((size_t)b*Nn_ + i)*DN_;
    __shared__ int idxs[Nn_];
    __shared__ int cnt;
    if (t == 0) cnt = 0;
    __syncthreads();
    if (i >= no) {
        for (int c = t; c < DN_; c += 128) { Xrow[c] = 0.f; Trow[c] = 0.f; }
        return;
    }
    const float* arow = adj + ((size_t)b*Nn_ + i)*Nn_;
    const float* nfb  = nf  + (size_t)b*Nn_*DN_;
    if (t < no && arow[t] != 0.f) { int p = atomicAdd(&cnt, 1); idxs[p] = t; }
    __syncthreads();
    int nn = cnt;
    for (int c = t; c < DN_; c += 128) {
        float x = nfb[(size_t)i*DN_ + c];
        float acc = x;                               // + eye * nmask_i  term
        for (int e = 0; e < nn; e++) acc += nfb[(size_t)idxs[e]*DN_ + c];
        Xrow[c] = x;
        Trow[c] = acc;
    }
}

// ---------------- K2: gather Eg[b,m] = ef[b,src,dst] * emask ------------------
__global__ void k_eg(const float* __restrict__ ef, const int* __restrict__ ei,
                     const int* __restrict__ num_edges) {
    int b = blockIdx.y, m = blockIdx.x, t = threadIdx.x;   // 64 threads, float4
    float4* dst = (float4*)(d_Eg + ((size_t)b*Mm + m)*DE_);
    if (m >= num_edges[b]) { dst[t] = make_float4(0.f,0.f,0.f,0.f); return; }
    int s = ei[(b*2 + 0)*Mm + m];
    int d = ei[(b*2 + 1)*Mm + m];
    const float4* src = (const float4*)(ef + (((size_t)b*Nn_ + s)*Nn_ + d)*DE_);
    dst[t] = src[t];
}

// ---------------- K3: T1 = L @ Eg  (sparse, per-row compaction) ---------------
__global__ void k_lspmm(const float* __restrict__ ladj, const int* __restrict__ num_edges) {
    int b = blockIdx.y, i = blockIdx.x, t = threadIdx.x;   // 256 threads
    int ne = num_edges[b];
    float* Trow = d_T1 + ((size_t)b*Mm + i)*DE_;
    __shared__ int idxs[Mm];
    __shared__ int cnt;
    if (t == 0) cnt = 0;
    __syncthreads();
    if (i >= ne) { Trow[t] = 0.f; return; }                // DE_ == blockDim
    const float* lrow = ladj + ((size_t)b*Mm + i)*Mm;
    const float* Egb  = d_Eg + (size_t)b*Mm*DE_;
    for (int j = t; j < ne; j += 256)
        if (lrow[j] != 0.f) { int p = atomicAdd(&cnt, 1); idxs[p] = j; }
    __syncthreads();
    int nn = cnt;
    float acc = Egb[(size_t)i*DE_ + t];                    // + eye term
    for (int e = 0; e < nn; e++) acc += Egb[(size_t)idxs[e]*DE_ + t];
    Trow[t] = acc;
}

// ---------------- K4: zero + scatter agg -------------------------------------
__global__ void k_zero(float* p, int n) {
    int i = blockIdx.x*blockDim.x + threadIdx.x;
    if (i < n) p[i] = 0.f;
}
__global__ void k_scatter(const int* __restrict__ ei) {
    int b = blockIdx.y, m = blockIdx.x, t = threadIdx.x;   // 128 threads
    int s = ei[(b*2 + 0)*Mm + m];
    float v = d_g[((size_t)b*Mm + m)*WE_ + t];
    if (v != 0.f) atomicAdd(&d_agg[((size_t)b*Nn_ + s)*WE_ + t], v);
}

// ---------------- K5: gather edge feats at pairs ------------------------------
__global__ void k_efp(const float* __restrict__ ef, const int* __restrict__ op) {
    int b = blockIdx.y, p = blockIdx.x, t = threadIdx.x;   // 64 threads, float4
    int p0 = op[((size_t)b*Pp + p)*2 + 0];
    int p1 = op[((size_t)b*Pp + p)*2 + 1];
    const float4* src = (const float4*)(ef + (((size_t)b*Nn_ + p0)*Nn_ + p1)*DE_);
    ((float4*)(d_efp + ((size_t)b*Pp + p)*DE_))[t] = src[t];
}

// ---------------- K6: assemble ci columns [0,384) -----------------------------
__global__ void k_ci(const int* __restrict__ op, const int* __restrict__ num_obj) {
    int b = blockIdx.y, p = blockIdx.x, t = threadIdx.x;   // 128 threads
    int p0 = op[((size_t)b*Pp + p)*2 + 0];
    int p1 = op[((size_t)b*Pp + p)*2 + 1];
    int no = num_obj[b];
    float m0 = (p0 < no) ? 1.f : 0.f;
    float m1 = (p1 < no) ? 1.f : 0.f;
    float* ci = d_ci + ((size_t)b*Pp + p)*512;
    const float* h0 = d_h   + ((size_t)b*Nn_ + p0)*WN_;
    const float* h1 = d_h   + ((size_t)b*Nn_ + p1)*WN_;
    const float* a0 = d_agg + ((size_t)b*Nn_ + p0)*WE_;
    const float* a1 = d_agg + ((size_t)b*Nn_ + p1)*WE_;
    const float* x0 = d_Xp  + ((size_t)b*Nn_ + p0)*WN_;
    const float* x1 = d_Xp  + ((size_t)b*Nn_ + p1)*WN_;
    ci[t]       = h0[t] + h1[t];
    ci[128 + t] = a0[t]*m0 + a1[t]*m1;
    ci[256 + t] = fmaxf(x0[t] + x1[t], 0.f);
    // cols [384,512) filled by the Q GEMM
}

// ---------------- SGEMM 128x128x8 fp32 with f32x2 packed FMA ------------------
template<bool RELU, bool BIAS>
__global__ void __launch_bounds__(256, 2)
sgemm(const float* __restrict__ A, const float* __restrict__ Bm,
      const float* __restrict__ bias, float* __restrict__ C,
      int M, int K, int Ncols, int ldc) {
    __shared__ float As[8][128];
    __shared__ float Bs[8][128];
    int t  = threadIdx.x;
    int rb = blockIdx.y * 128, cb = blockIdx.x * 128;
    int tx = t & 15, ty = t >> 4;
    int arow = t >> 1,  acol = (t & 1) * 4;
    int brow = t >> 5,  bcol = (t & 31) * 4;
    unsigned long long acc[8][4];
    #pragma unroll
    for (int i = 0; i < 8; i++)
        #pragma unroll
        for (int j = 0; j < 4; j++) acc[i][j] = 0ull;

    for (int k0 = 0; k0 < K; k0 += 8) {
        float4 av = *(const float4*)(A  + (size_t)(rb + arow)*K + k0 + acol);
        float4 bv = *(const float4*)(Bm + (size_t)(k0 + brow)*Ncols + cb + bcol);
        __syncthreads();
        As[acol+0][arow] = av.x; As[acol+1][arow] = av.y;
        As[acol+2][arow] = av.z; As[acol+3][arow] = av.w;
        *(float4*)&Bs[brow][bcol] = bv;
        __syncthreads();
        #pragma unroll
        for (int kk = 0; kk < 8; kk++) {
            float4 a0 = *(const float4*)&As[kk][ty*8];
            float4 a1 = *(const float4*)&As[kk][ty*8 + 4];
            float4 b0 = *(const float4*)&Bs[kk][tx*8];
            float4 b1 = *(const float4*)&Bs[kk][tx*8 + 4];
            unsigned long long b2[4] = { pk2(b0.x,b0.y), pk2(b0.z,b0.w),
                                         pk2(b1.x,b1.y), pk2(b1.z,b1.w) };
            float a[8] = {a0.x,a0.y,a0.z,a0.w,a1.x,a1.y,a1.z,a1.w};
            #pragma unroll
            for (int i = 0; i < 8; i++) {
                unsigned long long a2 = pk2(a[i], a[i]);
                ffma2(acc[i][0], a2, b2[0]);
                ffma2(acc[i][1], a2, b2[1]);
                ffma2(acc[i][2], a2, b2[2]);
                ffma2(acc[i][3], a2, b2[3]);
            }
        }
    }
    #pragma unroll
    for (int i = 0; i < 8; i++) {
        int r = rb + ty*8 + i;
        float* crow = C + (size_t)r*ldc + cb + tx*8;
        #pragma unroll
        for (int j = 0; j < 4; j++) {
            float lo, hi;
            up2(acc[i][j], lo, hi);
            int c = tx*8 + 2*j;
            if (BIAS) { lo += bias[cb + c]; hi += bias[cb + c + 1]; }
            if (RELU) { lo = fmaxf(lo, 0.f); hi = fmaxf(hi, 0.f); }
            *(float2*)(crow + 2*j) = make_float2(lo, hi);
        }
    }
}

// ---------------- K7: MLP layer 2, three heads fused --------------------------
__global__ void k_head(const float* __restrict__ Wl, const float* __restrict__ bl,
                       const float* __restrict__ Wc, const float* __restrict__ bc,
                       const float* __restrict__ Wm, const float* __restrict__ bm,
                       float* __restrict__ out) {
    int r = blockIdx.x;          // row = b*P + p, 0..8191
    int t = threadIdx.x;         // 256
    __shared__ float hs[768];
    for (int c = t; c < 768; c += 256) {
        int head = c >> 8, cc = c & 255;
        hs[c] = d_hid[(size_t)head*((size_t)Bc*Pp*HID_) + (size_t)r*HID_ + cc];
    }
    __syncthreads();
    int o = t >> 3, l = t & 7;   // 32 outputs x 8 lanes
    const float* W; const float* bb; const float* hrow; int od, oc; float* dst;
    if (o < 9)       { W = Wl; bb = bl; hrow = hs;       od = 9;  oc = o;      dst = out +           (size_t)r*9  + oc; }
    else if (o < 15) { W = Wc; bb = bc; hrow = hs + 256; od = 6;  oc = o - 9;  dst = out + 73728  + (size_t)r*6  + oc; }
    else             { W = Wm; bb = bm; hrow = hs + 512; od = 17; oc = o - 15; dst = out + 122880 + (size_t)r*17 + oc; }
    float s = 0.f;
    for (int k = l; k < 256; k += 8) s += hrow[k] * W[(size_t)k*od + oc];
    #pragma unroll
    for (int off = 4; off; off >>= 1) s += __shfl_down_sync(0xffffffffu, s, off, 8);
    if (l == 0) *dst = s + bb[oc];
}

// ---------------- launch -----------------------------------------------------
extern "C" void kernel_launch(void* const* d_in, const int* in_sizes, int n_in,
                              void* d_out, int out_size) {
    const float* nf   = (const float*)d_in[0];
    const float* ef   = (const float*)d_in[1];
    const float* adj  = (const float*)d_in[2];
    const float* ladj = (const float*)d_in[3];
    const int*   ei   = (const int*)  d_in[4];
    const int*   op   = (const int*)  d_in[5];
    const int*   nob  = (const int*)  d_in[6];
    const int*   ned  = (const int*)  d_in[7];
    const float* Wn   = (const float*)d_in[8];
    const float* We   = (const float*)d_in[9];
    const float* Wn2  = (const float*)d_in[10];
    const float* We2  = (const float*)d_in[11];
    const float* scrW1= (const float*)d_in[12];
    const float* scrb1= (const float*)d_in[13];
    const float* scrW2= (const float*)d_in[14];
    const float* scrb2= (const float*)d_in[15];
    const float* lrW1 = (const float*)d_in[16];
    const float* lrb1 = (const float*)d_in[17];
    const float* lrW2 = (const float*)d_in[18];
    const float* lrb2 = (const float*)d_in[19];
    const float* mrW1 = (const float*)d_in[20];
    const float* mrb1 = (const float*)d_in[21];
    const float* mrW2 = (const float*)d_in[22];
    const float* mrb2 = (const float*)d_in[23];
    float* out = (float*)d_out;

    float *pX, *pT2, *pT1, *pEfp, *pCi, *pHid, *pH, *pXp, *pG, *pAgg;
    cudaGetSymbolAddress((void**)&pX,   d_X);
    cudaGetSymbolAddress((void**)&pT2,  d_T2);
    cudaGetSymbolAddress((void**)&pT1,  d_T1);
    cudaGetSymbolAddress((void**)&pEfp, d_efp);
    cudaGetSymbolAddress((void**)&pCi,  d_ci);
    cudaGetSymbolAddress((void**)&pHid, d_hid);
    cudaGetSymbolAddress((void**)&pH,   d_h);
    cudaGetSymbolAddress((void**)&pXp,  d_Xp);
    cudaGetSymbolAddress((void**)&pG,   d_g);
    cudaGetSymbolAddress((void**)&pAgg, d_agg);

    // node path
    k_zero<<<(Bc*Nn_*WE_ + 255)/256, 256>>>(pAgg, Bc*Nn_*WE_);
    k_ax<<<dim3(Nn_, Bc), 128>>>(nf, adj, nob);
    // edge path
    k_eg<<<dim3(Mm, Bc), 64>>>(ef, ei, ned);
    k_lspmm<<<dim3(Mm, Bc), 256>>>(ladj, ned);
    // g = relu(T1 @ We)   [16384 x 256 x 128]
    sgemm<true,false><<<dim3(1, (Bc*Mm)/128), 256>>>(pT1, We, nullptr, pG,
                                                     Bc*Mm, DE_, WE_, WE_);
    k_scatter<<<dim3(Mm, Bc), 128>>>(ei);
    // h = relu(T2 @ Wn)   [2048 x 512 x 128]
    sgemm<true,false><<<dim3(1, (Bc*Nn_)/128), 256>>>(pT2, Wn, nullptr, pH,
                                                      Bc*Nn_, DN_, WN_, WN_);
    // Xp = X @ Wn2        [2048 x 512 x 128]
    sgemm<false,false><<<dim3(1, (Bc*Nn_)/128), 256>>>(pX, Wn2, nullptr, pXp,
                                                       Bc*Nn_, DN_, WN_, WN_);
    // pair path
    k_efp<<<dim3(Pp, Bc), 64>>>(ef, op);
    // Q = relu(efp @ We2) -> ci[:,384:512]   [8192 x 256 x 128]
    sgemm<true,false><<<dim3(1, (Bc*Pp)/128), 256>>>(pEfp, We2, nullptr, pCi + 384,
                                                     Bc*Pp, DE_, WE_, 512);
    k_ci<<<dim3(Pp, Bc), 128>>>(op, nob);
    // MLP layer 1, three heads  [8192 x 512 x 256] each
    size_t hstride = (size_t)Bc*Pp*HID_;
    sgemm<true,true><<<dim3(2, (Bc*Pp)/128), 256>>>(pCi, lrW1,  lrb1,  pHid,             Bc*Pp, 512, HID_, HID_);
    sgemm<true,true><<<dim3(2, (Bc*Pp)/128), 256>>>(pCi, scrW1, scrb1, pHid + hstride,   Bc*Pp, 512, HID_, HID_);
    sgemm<true,true><<<dim3(2, (Bc*Pp)/128), 256>>>(pCi, mrW1,  mrb1,  pHid + 2*hstride, Bc*Pp, 512, HID_, HID_);
    // MLP layer 2 fused across heads -> output
    k_head<<<Bc*Pp, 256>>>(lrW2, lrb2, scrW2, scrb2, mrW2, mrb2, out);
}

// round 3
// speedup vs baseline: 1.8270x; 1.8270x over previous
#include <cuda_runtime.h>
#include <cuda_bf16.h>
#include <mma.h>
#include <cstdint>

using namespace nvcuda;

// Problem constants
#define Bc   16
#define Nn_  128
#define Mm   1024
#define DN_  512
#define DE_  256
#define WN_  128
#define WE_  128
#define Pp   512
#define HID_ 256

// ---------------- scratch (static device globals; no allocation) -------------
__device__ float d_X  [(size_t)Bc*Nn_*DN_];
__device__ float d_T2 [(size_t)Bc*Nn_*DN_];
__device__ float d_h  [(size_t)Bc*Nn_*WN_];
__device__ float d_Xp [(size_t)Bc*Nn_*WN_];
__device__ float d_Eg [(size_t)Bc*Mm*DE_];
__device__ float d_T1 [(size_t)Bc*Mm*DE_];
__device__ float d_g  [(size_t)Bc*Mm*WE_];
__device__ float d_agg[(size_t)Bc*Nn_*WE_];
__device__ float d_efp[(size_t)Bc*Pp*DE_];
__device__ float d_ci [(size_t)Bc*Pp*512];
__device__ float d_hid[(size_t)Bc*Pp*768];        // [row][768] interleaved heads
__device__ __nv_bfloat16 d_WtH[589824];           // transposed weights, bf16 hi
__device__ __nv_bfloat16 d_WtL[589824];           // transposed weights, bf16 lo
__device__ float d_b1cat[768];                    // concat(lrb1, scrb1, mrb1)

// ---------------- K: weight transpose + bf16 split ---------------------------
__global__ void k_wt(const float* __restrict__ W, __nv_bfloat16* __restrict__ oh,
                     __nv_bfloat16* __restrict__ ol, int K, int N) {
    int id = blockIdx.x * 256 + threadIdx.x;
    if (id >= K * N) return;
    int n = id / K, k = id % K;
    float w = W[(size_t)k * N + n];
    __nv_bfloat16 h = __float2bfloat16(w);
    float lo = w - __bfloat162float(h);
    oh[id] = h;
    ol[id] = __float2bfloat16(lo);
}
__global__ void k_cat(const float* __restrict__ a, const float* __restrict__ b,
                      const float* __restrict__ c) {
    int t = blockIdx.x * 256 + threadIdx.x;
    if (t < 256)       d_b1cat[t]       = a[t];
    else if (t < 512)  d_b1cat[t]       = b[t - 256];
    else if (t < 768)  d_b1cat[t]       = c[t - 512];
}

// ---------------- wmma bf16 split-precision GEMM ------------------------------
// C[rb:+128, col_off+cb:+128] = A(fp32 [M,K]) @ Bt^T  (Bt bf16 hi/lo [N][K])
// acc += Ah*Bh + Ah*Bl + Al*Bh   (fp32 accumulate)
#define LDS_T 40      // bf16 tile row stride (padding -> conflict-free ldmatrix)
#define LDS_S 132     // fp32 stage row stride

template<bool RELU, bool BIAS>
__global__ void __launch_bounds__(256, 2)
wgemm(const float* __restrict__ A, const __nv_bfloat16* __restrict__ BtH,
      const __nv_bfloat16* __restrict__ BtL, const float* __restrict__ bias,
      float* __restrict__ C, int K, int ldc, int col_off) {
    extern __shared__ char smem[];
    __nv_bfloat16* Ah = (__nv_bfloat16*)smem;       // [128][LDS_T]
    __nv_bfloat16* Al = Ah + 128 * LDS_T;
    __nv_bfloat16* Bh = Al + 128 * LDS_T;
    __nv_bfloat16* Bl = Bh + 128 * LDS_T;

    int t = threadIdx.x, wid = t >> 5;
    int rb = blockIdx.y * 128, cb = blockIdx.x * 128;
    int wm = wid & 3, wn = wid >> 2;   // warp tile: rows wm*32, cols wn*64

    wmma::fragment<wmma::accumulator, 16, 16, 16, float> acc[2][4];
    #pragma unroll
    for (int m = 0; m < 2; m++)
        #pragma unroll
        for (int n = 0; n < 4; n++) wmma::fill_fragment(acc[m][n], 0.0f);

    const int row = t >> 1, half = t & 1;          // each thread: 16 elements

    for (int k0 = 0; k0 < K; k0 += 32) {
        __syncthreads();
        // ---- A chunk: fp32 -> bf16 hi/lo ----
        {
            const float* ap = A + (size_t)(rb + row) * K + k0 + half * 16;
            __nv_bfloat16* dh = Ah + row * LDS_T + half * 16;
            __nv_bfloat16* dl = Al + row * LDS_T + half * 16;
            #pragma unroll
            for (int q = 0; q < 4; q++) {
                float4 v = *(const float4*)(ap + q * 4);
                __nv_bfloat16 h0 = __float2bfloat16(v.x), h1 = __float2bfloat16(v.y);
                __nv_bfloat16 h2 = __float2bfloat16(v.z), h3 = __float2bfloat16(v.w);
                uint2 hp, lp;
                hp.x = (uint32_t)__bfloat16_as_ushort(h0) | ((uint32_t)__bfloat16_as_ushort(h1) << 16);
                hp.y = (uint32_t)__bfloat16_as_ushort(h2) | ((uint32_t)__bfloat16_as_ushort(h3) << 16);
                __nv_bfloat16 l0 = __float2bfloat16(v.x - __bfloat162float(h0));
                __nv_bfloat16 l1 = __float2bfloat16(v.y - __bfloat162float(h1));
                __nv_bfloat16 l2 = __float2bfloat16(v.z - __bfloat162float(h2));
                __nv_bfloat16 l3 = __float2bfloat16(v.w - __bfloat162float(h3));
                lp.x = (uint32_t)__bfloat16_as_ushort(l0) | ((uint32_t)__bfloat16_as_ushort(l1) << 16);
                lp.y = (uint32_t)__bfloat16_as_ushort(l2) | ((uint32_t)__bfloat16_as_ushort(l3) << 16);
                *(uint2*)(dh + q * 4) = hp;
                *(uint2*)(dl + q * 4) = lp;
            }
        }
        // ---- B chunk: bf16 copy ----
        {
            const __nv_bfloat16* bhp = BtH + (size_t)(cb + row) * K + k0 + half * 16;
            const __nv_bfloat16* blp = BtL + (size_t)(cb + row) * K + k0 + half * 16;
            uint4 vh = *(const uint4*)bhp;
            uint4 vl = *(const uint4*)blp;
            uint4 vh2 = *(const uint4*)(bhp + 8);
            uint4 vl2 = *(const uint4*)(blp + 8);
            *(uint4*)(Bh + row * LDS_T + half * 16)     = vh;
            *(uint4*)(Bh + row * LDS_T + half * 16 + 8) = vh2;
            *(uint4*)(Bl + row * LDS_T + half * 16)     = vl;
            *(uint4*)(Bl + row * LDS_T + half * 16 + 8) = vl2;
        }
        __syncthreads();
        // ---- compute: 2 k-steps of 16 ----
        #pragma unroll
        for (int kk = 0; kk < 2; kk++) {
            wmma::fragment<wmma::matrix_a, 16, 16, 16, __nv_bfloat16, wmma::row_major> fah[2], fal[2];
            #pragma unroll
            for (int m = 0; m < 2; m++) {
                wmma::load_matrix_sync(fah[m], Ah + (wm * 32 + m * 16) * LDS_T + kk * 16, LDS_T);
                wmma::load_matrix_sync(fal[m], Al + (wm * 32 + m * 16) * LDS_T + kk * 16, LDS_T);
            }
            #pragma unroll
            for (int n = 0; n < 4; n++) {
                wmma::fragment<wmma::matrix_b, 16, 16, 16, __nv_bfloat16, wmma::col_major> fbh, fbl;
                wmma::load_matrix_sync(fbh, Bh + (wn * 64 + n * 16) * LDS_T + kk * 16, LDS_T);
                wmma::load_matrix_sync(fbl, Bl + (wn * 64 + n * 16) * LDS_T + kk * 16, LDS_T);
                #pragma unroll
                for (int m = 0; m < 2; m++) {
                    wmma::mma_sync(acc[m][n], fah[m], fbh, acc[m][n]);
                    wmma::mma_sync(acc[m][n], fah[m], fbl, acc[m][n]);
                    wmma::mma_sync(acc[m][n], fal[m], fbh, acc[m][n]);
                }
            }
        }
    }

    // ---- epilogue: stage fp32 in smem, then bias/relu + coalesced store ----
    __syncthreads();
    float* stage = (float*)smem;                    // [128][LDS_S]
    #pragma unroll
    for (int m = 0; m < 2; m++)
        #pragma unroll
        for (int n = 0; n < 4; n++)
            wmma::store_matrix_sync(stage + (wm * 32 + m * 16) * LDS_S + wn * 64 + n * 16,
                                    acc[m][n], LDS_S, wmma::mem_row_major);
    __syncthreads();
    {
        int r = t >> 1, ch = (t & 1) * 64;
        float* crow = C + (size_t)(rb + r) * ldc + col_off + cb + ch;
        const float* srow = stage + r * LDS_S + ch;
        #pragma unroll
        for (int q = 0; q < 16; q++) {
            float4 v = *(const float4*)(srow + q * 4);
            if (BIAS) {
                int gc = cb + ch + q * 4;
                v.x += bias[gc + 0]; v.y += bias[gc + 1];
                v.z += bias[gc + 2]; v.w += bias[gc + 3];
            }
            if (RELU) {
                v.x = fmaxf(v.x, 0.f); v.y = fmaxf(v.y, 0.f);
                v.z = fmaxf(v.z, 0.f); v.w = fmaxf(v.w, 0.f);
            }
            *(float4*)(crow + q * 4) = v;
        }
    }
}

// ---------------- K1: X = nf*nmask ; T2 = A @ X  (sparse, per-row) -----------
__global__ void k_ax(const float* __restrict__ nf, const float* __restrict__ adj,
                     const int* __restrict__ num_obj) {
    int b = blockIdx.y, i = blockIdx.x, t = threadIdx.x;   // 128 threads
    int no = num_obj[b];
    float* Xrow = d_X  + ((size_t)b*Nn_ + i)*DN_;
    float* Trow = d_T2 + ((size_t)b*Nn_ + i)*DN_;
    __shared__ int idxs[Nn_];
    __shared__ int cnt;
    if (t == 0) cnt = 0;
    __syncthreads();
    if (i >= no) {
        for (int c = t; c < DN_; c += 128) { Xrow[c] = 0.f; Trow[c] = 0.f; }
        return;
    }
    const float* arow = adj + ((size_t)b*Nn_ + i)*Nn_;
    const float* nfb  = nf  + (size_t)b*Nn_*DN_;
    if (t < no && arow[t] != 0.f) { int p = atomicAdd(&cnt, 1); idxs[p] = t; }
    __syncthreads();
    int nn = cnt;
    for (int c = t; c < DN_; c += 128) {
        float x = nfb[(size_t)i*DN_ + c];
        float acc = x;
        for (int e = 0; e < nn; e++) acc += nfb[(size_t)idxs[e]*DN_ + c];
        Xrow[c] = x;
        Trow[c] = acc;
    }
}

// ---------------- K2: gather Eg[b,m] = ef[b,src,dst] * emask ------------------
__global__ void k_eg(const float* __restrict__ ef, const int* __restrict__ ei,
                     const int* __restrict__ num_edges) {
    int b = blockIdx.y, m = blockIdx.x, t = threadIdx.x;   // 64 threads, float4
    float4* dst = (float4*)(d_Eg + ((size_t)b*Mm + m)*DE_);
    if (m >= num_edges[b]) { dst[t] = make_float4(0.f,0.f,0.f,0.f); return; }
    int s = ei[(b*2 + 0)*Mm + m];
    int d = ei[(b*2 + 1)*Mm + m];
    const float4* src = (const float4*)(ef + (((size_t)b*Nn_ + s)*Nn_ + d)*DE_);
    dst[t] = src[t];
}

// ---------------- K3: T1 = L @ Eg  (sparse, vectorized scan) ------------------
__global__ void k_lspmm(const float* __restrict__ ladj, const int* __restrict__ num_edges) {
    int b = blockIdx.y, i = blockIdx.x, t = threadIdx.x;   // 256 threads
    int ne = num_edges[b];
    float* Trow = d_T1 + ((size_t)b*Mm + i)*DE_;
    __shared__ int idxs[Mm];
    __shared__ int cnt;
    if (t == 0) cnt = 0;
    __syncthreads();
    if (i >= ne) { Trow[t] = 0.f; return; }
    const float4* lrow4 = (const float4*)(ladj + ((size_t)b*Mm + i)*Mm);
    float4 v = lrow4[t];
    int base = t * 4;
    if (base     < ne && v.x != 0.f) idxs[atomicAdd(&cnt, 1)] = base;
    if (base + 1 < ne && v.y != 0.f) idxs[atomicAdd(&cnt, 1)] = base + 1;
    if (base + 2 < ne && v.z != 0.f) idxs[atomicAdd(&cnt, 1)] = base + 2;
    if (base + 3 < ne && v.w != 0.f) idxs[atomicAdd(&cnt, 1)] = base + 3;
    __syncthreads();
    int nn = cnt;
    const float* Egb = d_Eg + (size_t)b*Mm*DE_;
    float acc = Egb[(size_t)i*DE_ + t];
    for (int e = 0; e < nn; e++) acc += Egb[(size_t)idxs[e]*DE_ + t];
    Trow[t] = acc;
}

// ---------------- K4: zero + scatter agg -------------------------------------
__global__ void k_zero(float* p, int n) {
    int i = blockIdx.x*blockDim.x + threadIdx.x;
    if (i < n) p[i] = 0.f;
}
__global__ void k_scatter(const int* __restrict__ ei) {
    int b = blockIdx.y, m = blockIdx.x, t = threadIdx.x;   // 128 threads
    int s = ei[(b*2 + 0)*Mm + m];
    float v = d_g[((size_t)b*Mm + m)*WE_ + t];
    if (v != 0.f) atomicAdd(&d_agg[((size_t)b*Nn_ + s)*WE_ + t], v);
}

// ---------------- K5: gather edge feats at pairs ------------------------------
__global__ void k_efp(const float* __restrict__ ef, const int* __restrict__ op) {
    int b = blockIdx.y, p = blockIdx.x, t = threadIdx.x;   // 64 threads, float4
    int p0 = op[((size_t)b*Pp + p)*2 + 0];
    int p1 = op[((size_t)b*Pp + p)*2 + 1];
    const float4* src = (const float4*)(ef + (((size_t)b*Nn_ + p0)*Nn_ + p1)*DE_);
    ((float4*)(d_efp + ((size_t)b*Pp + p)*DE_))[t] = src[t];
}

// ---------------- K6: assemble ci columns [0,384) -----------------------------
__global__ void k_ci(const int* __restrict__ op, const int* __restrict__ num_obj) {
    int b = blockIdx.y, p = blockIdx.x, t = threadIdx.x;   // 128 threads
    int p0 = op[((size_t)b*Pp + p)*2 + 0];
    int p1 = op[((size_t)b*Pp + p)*2 + 1];
    int no = num_obj[b];
    float m0 = (p0 < no) ? 1.f : 0.f;
    float m1 = (p1 < no) ? 1.f : 0.f;
    float* ci = d_ci + ((size_t)b*Pp + p)*512;
    const float* h0 = d_h   + ((size_t)b*Nn_ + p0)*WN_;
    const float* h1 = d_h   + ((size_t)b*Nn_ + p1)*WN_;
    const float* a0 = d_agg + ((size_t)b*Nn_ + p0)*WE_;
    const float* a1 = d_agg + ((size_t)b*Nn_ + p1)*WE_;
    const float* x0 = d_Xp  + ((size_t)b*Nn_ + p0)*WN_;
    const float* x1 = d_Xp  + ((size_t)b*Nn_ + p1)*WN_;
    ci[t]       = h0[t] + h1[t];
    ci[128 + t] = a0[t]*m0 + a1[t]*m1;
    ci[256 + t] = fmaxf(x0[t] + x1[t], 0.f);
}

// ---------------- K7: MLP layer 2, three heads fused --------------------------
__global__ void k_head(const float* __restrict__ Wl, const float* __restrict__ bl,
                       const float* __restrict__ Wc, const float* __restrict__ bc,
                       const float* __restrict__ Wm, const float* __restrict__ bm,
                       float* __restrict__ out) {
    int r = blockIdx.x;          // row = b*P + p
    int t = threadIdx.x;         // 256
    __shared__ float hs[768];
    for (int c = t; c < 768; c += 256) hs[c] = d_hid[(size_t)r*768 + c];
    __syncthreads();
    int o = t >> 3, l = t & 7;
    const float* W; const float* bb; const float* hrow; int od, oc; float* dst;
    if (o < 9)       { W = Wl; bb = bl; hrow = hs;       od = 9;  oc = o;      dst = out +           (size_t)r*9  + oc; }
    else if (o < 15) { W = Wc; bb = bc; hrow = hs + 256; od = 6;  oc = o - 9;  dst = out + 73728  + (size_t)r*6  + oc; }
    else             { W = Wm; bb = bm; hrow = hs + 512; od = 17; oc = o - 15; dst = out + 122880 + (size_t)r*17 + oc; }
    float s = 0.f;
    for (int k = l; k < 256; k += 8) s += hrow[k] * W[(size_t)k*od + oc];
    #pragma unroll
    for (int off = 4; off; off >>= 1) s += __shfl_down_sync(0xffffffffu, s, off, 8);
    if (l == 0) *dst = s + bb[oc];
}

// ---------------- launch -----------------------------------------------------
extern "C" void kernel_launch(void* const* d_in, const int* in_sizes, int n_in,
                              void* d_out, int out_size) {
    const float* nf   = (const float*)d_in[0];
    const float* ef   = (const float*)d_in[1];
    const float* adj  = (const float*)d_in[2];
    const float* ladj = (const float*)d_in[3];
    const int*   ei   = (const int*)  d_in[4];
    const int*   op   = (const int*)  d_in[5];
    const int*   nob  = (const int*)  d_in[6];
    const int*   ned  = (const int*)  d_in[7];
    const float* Wn   = (const float*)d_in[8];
    const float* We   = (const float*)d_in[9];
    const float* Wn2  = (const float*)d_in[10];
    const float* We2  = (const float*)d_in[11];
    const float* scrW1= (const float*)d_in[12];
    const float* scrb1= (const float*)d_in[13];
    const float* scrW2= (const float*)d_in[14];
    const float* scrb2= (const float*)d_in[15];
    const float* lrW1 = (const float*)d_in[16];
    const float* lrb1 = (const float*)d_in[17];
    const float* lrW2 = (const float*)d_in[18];
    const float* lrb2 = (const float*)d_in[19];
    const float* mrW1 = (const float*)d_in[20];
    const float* mrb1 = (const float*)d_in[21];
    const float* mrW2 = (const float*)d_in[22];
    const float* mrb2 = (const float*)d_in[23];
    float* out = (float*)d_out;

    float *pX, *pT2, *pT1, *pEfp, *pCi, *pHid, *pG, *pAgg, *pH2, *pXp2, *pB1;
    __nv_bfloat16 *pWtH, *pWtL;
    cudaGetSymbolAddress((void**)&pX,   d_X);
    cudaGetSymbolAddress((void**)&pT2,  d_T2);
    cudaGetSymbolAddress((void**)&pT1,  d_T1);
    cudaGetSymbolAddress((void**)&pEfp, d_efp);
    cudaGetSymbolAddress((void**)&pCi,  d_ci);
    cudaGetSymbolAddress((void**)&pHid, d_hid);
    cudaGetSymbolAddress((void**)&pG,   d_g);
    cudaGetSymbolAddress((void**)&pAgg, d_agg);
    cudaGetSymbolAddress((void**)&pH2,  d_h);
    cudaGetSymbolAddress((void**)&pXp2, d_Xp);
    cudaGetSymbolAddress((void**)&pWtH, d_WtH);
    cudaGetSymbolAddress((void**)&pWtL, d_WtL);
    cudaGetSymbolAddress((void**)&pB1,  d_b1cat);

    const int SMEM_BYTES = 128 * LDS_S * 4;   // 67584 (covers tiles too)
    cudaFuncSetAttribute(wgemm<true,false>,  cudaFuncAttributeMaxDynamicSharedMemorySize, SMEM_BYTES);
    cudaFuncSetAttribute(wgemm<false,false>, cudaFuncAttributeMaxDynamicSharedMemorySize, SMEM_BYTES);
    cudaFuncSetAttribute(wgemm<true,true>,   cudaFuncAttributeMaxDynamicSharedMemorySize, SMEM_BYTES);

    // weight offsets in d_Wt{H,L} (elements); lr/scr/mr contiguous -> [768][512]
    const size_t oWe = 0, oWn = 32768, oWn2 = 98304, oWe2 = 163840, oMlp = 196608;
    k_wt<<<(256*128 + 255)/256, 256>>>(We,    pWtH + oWe,  pWtL + oWe,  256, 128);
    k_wt<<<(512*128 + 255)/256, 256>>>(Wn,    pWtH + oWn,  pWtL + oWn,  512, 128);
    k_wt<<<(512*128 + 255)/256, 256>>>(Wn2,   pWtH + oWn2, pWtL + oWn2, 512, 128);
    k_wt<<<(256*128 + 255)/256, 256>>>(We2,   pWtH + oWe2, pWtL + oWe2, 256, 128);
    k_wt<<<(512*256 + 255)/256, 256>>>(lrW1,  pWtH + oMlp,          pWtL + oMlp,          512, 256);
    k_wt<<<(512*256 + 255)/256, 256>>>(scrW1, pWtH + oMlp + 131072, pWtL + oMlp + 131072, 512, 256);
    k_wt<<<(512*256 + 255)/256, 256>>>(mrW1,  pWtH + oMlp + 262144, pWtL + oMlp + 262144, 512, 256);
    k_cat<<<3, 256>>>(lrb1, scrb1, mrb1);

    // node path
    k_zero<<<(Bc*Nn_*WE_ + 255)/256, 256>>>(pAgg, Bc*Nn_*WE_);
    k_ax<<<dim3(Nn_, Bc), 128>>>(nf, adj, nob);
    // edge path
    k_eg<<<dim3(Mm, Bc), 64>>>(ef, ei, ned);
    k_lspmm<<<dim3(Mm, Bc), 256>>>(ladj, ned);
    // g = relu(T1 @ We)   [16384 x 256 x 128]
    wgemm<true,false><<<dim3(1, 128), 256, SMEM_BYTES>>>(pT1, pWtH + oWe, pWtL + oWe,
                                                         nullptr, pG, 256, WE_, 0);
    k_scatter<<<dim3(Mm, Bc), 128>>>(ei);
    // h = relu(T2 @ Wn)   [2048 x 512 x 128]
    wgemm<true,false><<<dim3(1, 16), 256, SMEM_BYTES>>>(pT2, pWtH + oWn, pWtL + oWn,
                                                        nullptr, pH2, 512, WN_, 0);
    // Xp = X @ Wn2        [2048 x 512 x 128]
    wgemm<false,false><<<dim3(1, 16), 256, SMEM_BYTES>>>(pX, pWtH + oWn2, pWtL + oWn2,
                                                         nullptr, pXp2, 512, WN_, 0);
    // pair path
    k_efp<<<dim3(Pp, Bc), 64>>>(ef, op);
    // Q = relu(efp @ We2) -> ci cols [384,512)   [8192 x 256 x 128]
    wgemm<true,false><<<dim3(1, 64), 256, SMEM_BYTES>>>(pEfp, pWtH + oWe2, pWtL + oWe2,
                                                        nullptr, pCi, 256, 512, 384);
    k_ci<<<dim3(Pp, Bc), 128>>>(op, nob);
    // MLP layer 1, all three heads fused: [8192 x 768 x 512] -> d_hid [r][768]
    wgemm<true,true><<<dim3(6, 64), 256, SMEM_BYTES>>>(pCi, pWtH + oMlp, pWtL + oMlp,
                                                       pB1, pHid, 512, 768, 0);
    // MLP layer 2 fused across heads -> output
    k_head<<<Bc*Pp, 256>>>(lrW2, lrb2, scrW2, scrb2, mrW2, mrb2, out);
}

// round 4
// speedup vs baseline: 2.2831x; 1.2496x over previous
#include <cuda_runtime.h>
#include <cuda_bf16.h>
#include <mma.h>
#include <cstdint>

using namespace nvcuda;
typedef __nv_bfloat16 bf16;

// Problem constants
#define Bc   16
#define Nn_  128
#define Mm   1024
#define DN_  512
#define DE_  256
#define WN_  128
#define WE_  128
#define Pp   512
#define HID_ 256

// ---------------- scratch (static device globals; no allocation) -------------
__device__ float d_Eg [(size_t)Bc*Mm*DE_];
__device__ float d_h  [(size_t)Bc*Nn_*WN_];
__device__ float d_Xp [(size_t)Bc*Nn_*WN_];
__device__ float d_agg[(size_t)Bc*Nn_*WE_];
__device__ float d_hid[(size_t)Bc*Pp*768];
__device__ float d_b1cat[768];

__device__ __align__(128) bf16 d_T1h[(size_t)Bc*Mm*DE_];
__device__ __align__(128) bf16 d_T1l[(size_t)Bc*Mm*DE_];
__device__ __align__(128) bf16 d_T2h[(size_t)Bc*Nn_*DN_];
__device__ __align__(128) bf16 d_T2l[(size_t)Bc*Nn_*DN_];
__device__ __align__(128) bf16 d_Xh [(size_t)Bc*Nn_*DN_];
__device__ __align__(128) bf16 d_Xl [(size_t)Bc*Nn_*DN_];
__device__ __align__(128) bf16 d_efph[(size_t)Bc*Pp*DE_];
__device__ __align__(128) bf16 d_efpl[(size_t)Bc*Pp*DE_];
__device__ __align__(128) bf16 d_cih[(size_t)Bc*Pp*512];
__device__ __align__(128) bf16 d_cil[(size_t)Bc*Pp*512];
__device__ __align__(128) bf16 d_WtH[589824];
__device__ __align__(128) bf16 d_WtL[589824];

// ---------------- helpers -----------------------------------------------------
__device__ __forceinline__ void split_store(bf16* H, bf16* L, size_t idx, float v) {
    bf16 h = __float2bfloat16(v);
    H[idx] = h;
    L[idx] = __float2bfloat16(v - __bfloat162float(h));
}
__device__ __forceinline__ uint32_t smem_u32(const void* p) {
    uint32_t a;
    asm("{ .reg .u64 t; cvta.to.shared.u64 t, %1; cvt.u32.u64 %0, t; }" : "=r"(a) : "l"(p));
    return a;
}
__device__ __forceinline__ void cpa16(uint32_t d, const void* s) {
    asm volatile("cp.async.cg.shared.global [%0], [%1], 16;" :: "r"(d), "l"(s));
}
#define CP_COMMIT() asm volatile("cp.async.commit_group;" ::: "memory")
#define CP_WAIT(n)  asm volatile("cp.async.wait_group %0;" :: "n"(n) : "memory")

// ---------------- K0: all weights transpose + split + bias concat -------------
struct WtTab {
    const float* W[7];
    int K[7], N[7];
    int off[7];        // element offset into d_Wt{H,L}
    int blkStart[8];   // cumulative block starts
    const float *b0, *b1, *b2;
};
__global__ void k_wt_all(WtTab tb, bf16* __restrict__ oh, bf16* __restrict__ ol,
                         float* __restrict__ bcat) {
    int bid = blockIdx.x;
    if (bid >= tb.blkStart[7]) {                   // 3 bias blocks
        int t = (bid - tb.blkStart[7]) * 256 + threadIdx.x;  // 0..767
        const float* src = (t < 256) ? tb.b0 : ((t < 512) ? tb.b1 : tb.b2);
        bcat[t] = src[t & 255];
        return;
    }
    int mi = 0;
    while (bid >= tb.blkStart[mi + 1]) mi++;
    int id = (bid - tb.blkStart[mi]) * 256 + threadIdx.x;
    int K = tb.K[mi], N = tb.N[mi];
    if (id >= K * N) return;
    int n = id / K, k = id % K;
    float w = tb.W[mi][(size_t)k * N + n];
    split_store(oh + tb.off[mi], ol + tb.off[mi], id, w);
}

// ---------------- K1: fused prep (zero agg | ax | eg | efp) -------------------
// grid layout: [0,2048) ax | [2048,18432) eg | [18432,26624) efp | [26624,28672) zero
__global__ void k_prep(const float* __restrict__ nf, const float* __restrict__ adj,
                       const int* __restrict__ nob, const float* __restrict__ ef,
                       const int* __restrict__ ei, const int* __restrict__ ned,
                       const int* __restrict__ op) {
    int bid = blockIdx.x, t = threadIdx.x;         // 128 threads
    __shared__ int idxs[Nn_];
    __shared__ int cnt;
    if (bid < 2048) {                              // ---- ax ----
        int b = bid >> 7, i = bid & 127;
        int no = nob[b];
        size_t rbase = ((size_t)b * Nn_ + i) * DN_;
        if (t == 0) cnt = 0;
        __syncthreads();
        if (i >= no) {
            for (int c = t; c < DN_; c += 128) {
                d_Xh[rbase + c] = __float2bfloat16(0.f);  d_Xl[rbase + c] = __float2bfloat16(0.f);
                d_T2h[rbase + c] = __float2bfloat16(0.f); d_T2l[rbase + c] = __float2bfloat16(0.f);
            }
            return;
        }
        const float* arow = adj + ((size_t)b * Nn_ + i) * Nn_;
        const float* nfb  = nf  + (size_t)b * Nn_ * DN_;
        if (t < no && arow[t] != 0.f) { int p = atomicAdd(&cnt, 1); idxs[p] = t; }
        __syncthreads();
        int nn = cnt;
        for (int c = t; c < DN_; c += 128) {
            float x = nfb[(size_t)i * DN_ + c];
            float acc = x;
            for (int e = 0; e < nn; e++) acc += nfb[(size_t)idxs[e] * DN_ + c];
            split_store(d_Xh,  d_Xl,  rbase + c, x);
            split_store(d_T2h, d_T2l, rbase + c, acc);
        }
    } else if (bid < 18432) {                      // ---- eg ----
        int id = bid - 2048;
        int b = id >> 10, m = id & 1023;
        float2* dst = (float2*)(d_Eg + ((size_t)b * Mm + m) * DE_);
        if (m >= ned[b]) { dst[t] = make_float2(0.f, 0.f); return; }
        int s = ei[(b * 2 + 0) * Mm + m];
        int d = ei[(b * 2 + 1) * Mm + m];
        dst[t] = ((const float2*)(ef + (((size_t)b * Nn_ + s) * Nn_ + d) * DE_))[t];
    } else if (bid < 26624) {                      // ---- efp ----
        int id = bid - 18432;
        int b = id >> 9, p = id & 511;
        int p0 = op[((size_t)b * Pp + p) * 2 + 0];
        int p1 = op[((size_t)b * Pp + p) * 2 + 1];
        float2 v = ((const float2*)(ef + (((size_t)b * Nn_ + p0) * Nn_ + p1) * DE_))[t];
        size_t base = ((size_t)b * Pp + p) * DE_ + t * 2;
        split_store(d_efph, d_efpl, base + 0, v.x);
        split_store(d_efph, d_efpl, base + 1, v.y);
    } else {                                       // ---- zero agg ----
        d_agg[(size_t)(bid - 26624) * 128 + t] = 0.f;
    }
}

// ---------------- K2: T1 = L @ Eg  (sparse) -> bf16 hi/lo ---------------------
__global__ void k_lspmm(const float* __restrict__ ladj, const int* __restrict__ ned) {
    int b = blockIdx.y, i = blockIdx.x, t = threadIdx.x;   // 256 threads
    int ne = ned[b];
    size_t rbase = ((size_t)b * Mm + i) * DE_;
    __shared__ int idxs[Mm];
    __shared__ int cnt;
    if (t == 0) cnt = 0;
    __syncthreads();
    if (i >= ne) {
        d_T1h[rbase + t] = __float2bfloat16(0.f);
        d_T1l[rbase + t] = __float2bfloat16(0.f);
        return;
    }
    const float4* lrow4 = (const float4*)(ladj + ((size_t)b * Mm + i) * Mm);
    float4 v = lrow4[t];
    int base = t * 4;
    if (base     < ne && v.x != 0.f) idxs[atomicAdd(&cnt, 1)] = base;
    if (base + 1 < ne && v.y != 0.f) idxs[atomicAdd(&cnt, 1)] = base + 1;
    if (base + 2 < ne && v.z != 0.f) idxs[atomicAdd(&cnt, 1)] = base + 2;
    if (base + 3 < ne && v.w != 0.f) idxs[atomicAdd(&cnt, 1)] = base + 3;
    __syncthreads();
    int nn = cnt;
    const float* Egb = d_Eg + (size_t)b * Mm * DE_;
    float acc = Egb[(size_t)i * DE_ + t];
    for (int e = 0; e < nn; e++) acc += Egb[(size_t)idxs[e] * DE_ + t];
    split_store(d_T1h, d_T1l, rbase + t, acc);
}

// ---------------- multi-segment wmma GEMM (cp.async double-buffered) ----------
#define F_RELU 1
#define F_BIAS 2
#define F_SPLIT 4
#define F_SCATTER 8
#define LDS_T 40
#define LDS_S 132
#define STAGE_B 40960          // 4 tiles * 128 * 40 * 2 bytes

struct Seg {
    const bf16 *Ah, *Al, *Bh, *Bl;
    const float* bias;
    float* Cf;
    bf16 *Ch, *Cl;
    const int* ei;
    float* agg;
    int K, ldc, colOff, flags, nColBlk, blkEnd;
};
struct SegTable { Seg s[4]; int nseg; };

__global__ void __launch_bounds__(256)
wgemm_multi(SegTable tab) {
    extern __shared__ char smem[];
    int bid = blockIdx.x, t = threadIdx.x, wid = t >> 5;
    int si = 0;
    while (si + 1 < tab.nseg && bid >= tab.s[si].blkEnd) si++;
    const Seg sg = tab.s[si];
    int blk0 = (si == 0) ? 0 : tab.s[si - 1].blkEnd;
    int local = bid - blk0;
    int rb = (local / sg.nColBlk) * 128;
    int cb = (local % sg.nColBlk) * 128;
    const int K = sg.K;
    const int nch = K >> 5;

    const uint32_t sm = smem_u32(smem);
    const int row = t >> 1, part = t & 1;

    wmma::fragment<wmma::accumulator, 16, 16, 16, float> acc[2][4];
    #pragma unroll
    for (int m = 0; m < 2; m++)
        #pragma unroll
        for (int n = 0; n < 4; n++) wmma::fill_fragment(acc[m][n], 0.0f);
    int wm = wid & 3, wn = wid >> 2;

    // async load of one 32-k chunk into buffer `buf`
    auto load_chunk = [&](int kc, int buf) {
        const bf16* gsrc[4] = {sg.Ah, sg.Al, sg.Bh, sg.Bl};
        int rbase[4] = {rb, rb, cb, cb};
        #pragma unroll
        for (int tile = 0; tile < 4; tile++) {
            const char* src = (const char*)(gsrc[tile] + (size_t)(rbase[tile] + row) * K + kc * 32) + part * 32;
            uint32_t dst = sm + buf * STAGE_B + tile * 10240 + row * 80 + part * 32;
            cpa16(dst, src);
            cpa16(dst + 16, src + 16);
        }
    };

    load_chunk(0, 0);
    CP_COMMIT();
    for (int kc = 0; kc < nch; kc++) {
        if (kc + 1 < nch) { load_chunk(kc + 1, (kc + 1) & 1); CP_COMMIT(); CP_WAIT(1); }
        else              { CP_WAIT(0); }
        __syncthreads();
        const bf16* Ahs = (const bf16*)(smem + (kc & 1) * STAGE_B);
        const bf16* Als = Ahs + 5120;
        const bf16* Bhs = Ahs + 10240;
        const bf16* Bls = Ahs + 15360;
        #pragma unroll
        for (int kk = 0; kk < 2; kk++) {
            wmma::fragment<wmma::matrix_a, 16, 16, 16, bf16, wmma::row_major> fah[2], fal[2];
            #pragma unroll
            for (int m = 0; m < 2; m++) {
                wmma::load_matrix_sync(fah[m], Ahs + (wm * 32 + m * 16) * LDS_T + kk * 16, LDS_T);
                wmma::load_matrix_sync(fal[m], Als + (wm * 32 + m * 16) * LDS_T + kk * 16, LDS_T);
            }
            #pragma unroll
            for (int n = 0; n < 4; n++) {
                wmma::fragment<wmma::matrix_b, 16, 16, 16, bf16, wmma::col_major> fbh, fbl;
                wmma::load_matrix_sync(fbh, Bhs + (wn * 64 + n * 16) * LDS_T + kk * 16, LDS_T);
                wmma::load_matrix_sync(fbl, Bls + (wn * 64 + n * 16) * LDS_T + kk * 16, LDS_T);
                #pragma unroll
                for (int m = 0; m < 2; m++) {
                    wmma::mma_sync(acc[m][n], fah[m], fbh, acc[m][n]);
                    wmma::mma_sync(acc[m][n], fah[m], fbl, acc[m][n]);
                    wmma::mma_sync(acc[m][n], fal[m], fbh, acc[m][n]);
                }
            }
        }
        __syncthreads();
    }

    // ---- epilogue ----
    float* stage = (float*)smem;
    #pragma unroll
    for (int m = 0; m < 2; m++)
        #pragma unroll
        for (int n = 0; n < 4; n++)
            wmma::store_matrix_sync(stage + (wm * 32 + m * 16) * LDS_S + wn * 64 + n * 16,
                                    acc[m][n], LDS_S, wmma::mem_row_major);
    __syncthreads();
    int r = t >> 1, ch = (t & 1) * 64;
    const float* srow = stage + r * LDS_S + ch;
    if (sg.flags & F_SCATTER) {
        int m = rb + r, b = m >> 10, mm = m & 1023;
        int s = sg.ei[(b * 2) * Mm + mm];
        float* dst = sg.agg + ((size_t)(b * Nn_ + s)) * WE_ + ch;
        for (int q = 0; q < 64; q++) {
            float v = fmaxf(srow[q], 0.f);
            if (v != 0.f) atomicAdd(dst + q, v);
        }
    } else if (sg.flags & F_SPLIT) {
        size_t base = (size_t)(rb + r) * sg.ldc + sg.colOff + cb + ch;
        for (int q = 0; q < 64; q++) {
            float v = srow[q];
            if (sg.flags & F_RELU) v = fmaxf(v, 0.f);
            split_store(sg.Ch, sg.Cl, base + q, v);
        }
    } else {
        float* crow = sg.Cf + (size_t)(rb + r) * sg.ldc + cb + ch;
        #pragma unroll 4
        for (int q = 0; q < 16; q++) {
            float4 v = *(const float4*)(srow + q * 4);
            if (sg.flags & F_BIAS) {
                int gc = cb + ch + q * 4;
                v.x += sg.bias[gc + 0]; v.y += sg.bias[gc + 1];
                v.z += sg.bias[gc + 2]; v.w += sg.bias[gc + 3];
            }
            if (sg.flags & F_RELU) {
                v.x = fmaxf(v.x, 0.f); v.y = fmaxf(v.y, 0.f);
                v.z = fmaxf(v.z, 0.f); v.w = fmaxf(v.w, 0.f);
            }
            *(float4*)(crow + q * 4) = v;
        }
    }
}

// ---------------- K5: assemble ci columns [0,384) -> bf16 splits --------------
__global__ void k_ci(const int* __restrict__ op, const int* __restrict__ nob) {
    int b = blockIdx.y, p = blockIdx.x, t = threadIdx.x;   // 128 threads
    int p0 = op[((size_t)b * Pp + p) * 2 + 0];
    int p1 = op[((size_t)b * Pp + p) * 2 + 1];
    int no = nob[b];
    float m0 = (p0 < no) ? 1.f : 0.f;
    float m1 = (p1 < no) ? 1.f : 0.f;
    size_t base = ((size_t)b * Pp + p) * 512;
    const float* h0 = d_h   + ((size_t)b * Nn_ + p0) * WN_;
    const float* h1 = d_h   + ((size_t)b * Nn_ + p1) * WN_;
    const float* a0 = d_agg + ((size_t)b * Nn_ + p0) * WE_;
    const float* a1 = d_agg + ((size_t)b * Nn_ + p1) * WE_;
    const float* x0 = d_Xp  + ((size_t)b * Nn_ + p0) * WN_;
    const float* x1 = d_Xp  + ((size_t)b * Nn_ + p1) * WN_;
    split_store(d_cih, d_cil, base + t,       h0[t] + h1[t]);
    split_store(d_cih, d_cil, base + 128 + t, a0[t] * m0 + a1[t] * m1);
    split_store(d_cih, d_cil, base + 256 + t, fmaxf(x0[t] + x1[t], 0.f));
}

// ---------------- K7: MLP layer 2, three heads fused --------------------------
__global__ void k_head(const float* __restrict__ Wl, const float* __restrict__ bl,
                       const float* __restrict__ Wc, const float* __restrict__ bc,
                       const float* __restrict__ Wm, const float* __restrict__ bm,
                       float* __restrict__ out) {
    int r = blockIdx.x;
    int t = threadIdx.x;        // 256
    __shared__ float hs[768];
    for (int c = t; c < 768; c += 256) hs[c] = d_hid[(size_t)r * 768 + c];
    __syncthreads();
    int o = t >> 3, l = t & 7;
    const float* W; const float* bb; const float* hrow; int od, oc; float* dst;
    if (o < 9)       { W = Wl; bb = bl; hrow = hs;       od = 9;  oc = o;      dst = out +          (size_t)r * 9  + oc; }
    else if (o < 15) { W = Wc; bb = bc; hrow = hs + 256; od = 6;  oc = o - 9;  dst = out + 73728  + (size_t)r * 6  + oc; }
    else             { W = Wm; bb = bm; hrow = hs + 512; od = 17; oc = o - 15; dst = out + 122880 + (size_t)r * 17 + oc; }
    float s = 0.f;
    for (int k = l; k < 256; k += 8) s += hrow[k] * W[(size_t)k * od + oc];
    #pragma unroll
    for (int off = 4; off; off >>= 1) s += __shfl_down_sync(0xffffffffu, s, off, 8);
    if (l == 0) *dst = s + bb[oc];
}

// ---------------- launch -----------------------------------------------------
extern "C" void kernel_launch(void* const* d_in, const int* in_sizes, int n_in,
                              void* d_out, int out_size) {
    const float* nf   = (const float*)d_in[0];
    const float* ef   = (const float*)d_in[1];
    const float* adj  = (const float*)d_in[2];
    const float* ladj = (const float*)d_in[3];
    const int*   ei   = (const int*)  d_in[4];
    const int*   op   = (const int*)  d_in[5];
    const int*   nob  = (const int*)  d_in[6];
    const int*   ned  = (const int*)  d_in[7];
    const float* Wn   = (const float*)d_in[8];
    const float* We   = (const float*)d_in[9];
    const float* Wn2  = (const float*)d_in[10];
    const float* We2  = (const float*)d_in[11];
    const float* scrW1= (const float*)d_in[12];
    const float* scrb1= (const float*)d_in[13];
    const float* scrW2= (const float*)d_in[14];
    const float* scrb2= (const float*)d_in[15];
    const float* lrW1 = (const float*)d_in[16];
    const float* lrb1 = (const float*)d_in[17];
    const float* lrW2 = (const float*)d_in[18];
    const float* lrb2 = (const float*)d_in[19];
    const float* mrW1 = (const float*)d_in[20];
    const float* mrb1 = (const float*)d_in[21];
    const float* mrW2 = (const float*)d_in[22];
    const float* mrb2 = (const float*)d_in[23];
    float* out = (float*)d_out;

    bf16 *pWtH, *pWtL, *pT1h, *pT1l, *pT2h, *pT2l, *pXh, *pXl, *pEfph, *pEfpl, *pCih, *pCil;
    float *pH, *pXp, *pAgg, *pHid, *pB1;
    cudaGetSymbolAddress((void**)&pWtH, d_WtH);
    cudaGetSymbolAddress((void**)&pWtL, d_WtL);
    cudaGetSymbolAddress((void**)&pT1h, d_T1h);
    cudaGetSymbolAddress((void**)&pT1l, d_T1l);
    cudaGetSymbolAddress((void**)&pT2h, d_T2h);
    cudaGetSymbolAddress((void**)&pT2l, d_T2l);
    cudaGetSymbolAddress((void**)&pXh,  d_Xh);
    cudaGetSymbolAddress((void**)&pXl,  d_Xl);
    cudaGetSymbolAddress((void**)&pEfph,d_efph);
    cudaGetSymbolAddress((void**)&pEfpl,d_efpl);
    cudaGetSymbolAddress((void**)&pCih, d_cih);
    cudaGetSymbolAddress((void**)&pCil, d_cil);
    cudaGetSymbolAddress((void**)&pH,   d_h);
    cudaGetSymbolAddress((void**)&pXp,  d_Xp);
    cudaGetSymbolAddress((void**)&pAgg, d_agg);
    cudaGetSymbolAddress((void**)&pHid, d_hid);
    cudaGetSymbolAddress((void**)&pB1,  d_b1cat);

    const int SMEM_BYTES = 2 * STAGE_B;   // 81920
    cudaFuncSetAttribute(wgemm_multi, cudaFuncAttributeMaxDynamicSharedMemorySize, SMEM_BYTES);

    // ---- K0: weights prep ----
    const int oWe = 0, oWn = 32768, oWn2 = 98304, oWe2 = 163840, oMlp = 196608;
    WtTab wt;
    const float* Ws[7] = {We, Wn, Wn2, We2, lrW1, scrW1, mrW1};
    int Ks[7] = {256, 512, 512, 256, 512, 512, 512};
    int Ns[7] = {128, 128, 128, 128, 256, 256, 256};
    int offs[7] = {oWe, oWn, oWn2, oWe2, oMlp, oMlp + 131072, oMlp + 262144};
    int bs = 0;
    for (int i = 0; i < 7; i++) {
        wt.W[i] = Ws[i]; wt.K[i] = Ks[i]; wt.N[i] = Ns[i]; wt.off[i] = offs[i];
        wt.blkStart[i] = bs;
        bs += (Ks[i] * Ns[i]) / 256;
    }
    wt.blkStart[7] = bs;
    wt.b0 = lrb1; wt.b1 = scrb1; wt.b2 = mrb1;
    k_wt_all<<<bs + 3, 256>>>(wt, pWtH, pWtL, pB1);

    // ---- K1: fused prep ----
    k_prep<<<28672, 128>>>(nf, adj, nob, ef, ei, ned, op);
    // ---- K2: line-graph SpMM ----
    k_lspmm<<<dim3(Mm, Bc), 256>>>(ladj, ned);

    // ---- K3: fused GEMM wave: g(scatter) + h + Xp + Q(split) ----
    SegTable t4 = {};
    t4.nseg = 4;
    // seg0: g = relu(T1 @ We) scattered into agg by src
    t4.s[0] = {pT1h, pT1l, pWtH + oWe, pWtL + oWe, nullptr, nullptr, nullptr, nullptr,
               ei, pAgg, 256, 0, 0, F_RELU | F_SCATTER, 1, 128};
    // seg1: h = relu(T2 @ Wn)
    t4.s[1] = {pT2h, pT2l, pWtH + oWn, pWtL + oWn, nullptr, pH, nullptr, nullptr,
               nullptr, nullptr, 512, 128, 0, F_RELU, 1, 144};
    // seg2: Xp = X @ Wn2
    t4.s[2] = {pXh, pXl, pWtH + oWn2, pWtL + oWn2, nullptr, pXp, nullptr, nullptr,
               nullptr, nullptr, 512, 128, 0, 0, 1, 160};
    // seg3: Q = relu(efp @ We2) -> ci cols [384,512) as bf16 splits
    t4.s[3] = {pEfph, pEfpl, pWtH + oWe2, pWtL + oWe2, nullptr, nullptr, pCih, pCil,
               nullptr, nullptr, 256, 512, 384, F_RELU | F_SPLIT, 1, 224};
    wgemm_multi<<<224, 256, SMEM_BYTES>>>(t4);

    // ---- K4: ci assembly (cols 0..383) ----
    k_ci<<<dim3(Pp, Bc), 128>>>(op, nob);

    // ---- K5: MLP layer 1 fused heads [8192 x 768 x 512] ----
    SegTable t1 = {};
    t1.nseg = 1;
    t1.s[0] = {pCih, pCil, pWtH + oMlp, pWtL + oMlp, pB1, pHid, nullptr, nullptr,
               nullptr, nullptr, 512, 768, 0, F_RELU | F_BIAS, 6, 384};
    wgemm_multi<<<384, 256, SMEM_BYTES>>>(t1);

    // ---- K6: MLP layer 2 -> out ----
    k_head<<<Bc*Pp, 256>>>(lrW2, lrb2, scrW2, scrb2, mrW2, mrb2, out);
}

// round 5
// speedup vs baseline: 2.6790x; 1.1734x over previous
#include <cuda_runtime.h>
#include <cuda_bf16.h>
#include <mma.h>
#include <cstdint>

using namespace nvcuda;
typedef __nv_bfloat16 bf16;

// Problem constants
#define Bc   16
#define Nn_  128
#define Mm   1024
#define DN_  512
#define DE_  256
#define WN_  128
#define WE_  128
#define Pp   512
#define HID_ 256

// ---------------- scratch (static device globals; no allocation) -------------
__device__ float d_Eg [(size_t)Bc*Mm*DE_];
__device__ float d_h  [(size_t)Bc*Nn_*WN_];
__device__ float d_Xp [(size_t)Bc*Nn_*WN_];
__device__ float d_agg[(size_t)Bc*Nn_*WE_];
__device__ float d_hid[(size_t)Bc*Pp*768];
__device__ float d_b1cat[768];

__device__ __align__(128) bf16 d_T1h[(size_t)Bc*Mm*DE_];
__device__ __align__(128) bf16 d_T1l[(size_t)Bc*Mm*DE_];
__device__ __align__(128) bf16 d_T2h[(size_t)Bc*Nn_*DN_];
__device__ __align__(128) bf16 d_T2l[(size_t)Bc*Nn_*DN_];
__device__ __align__(128) bf16 d_Xh [(size_t)Bc*Nn_*DN_];
__device__ __align__(128) bf16 d_Xl [(size_t)Bc*Nn_*DN_];
__device__ __align__(128) bf16 d_efph[(size_t)Bc*Pp*DE_];
__device__ __align__(128) bf16 d_efpl[(size_t)Bc*Pp*DE_];
__device__ __align__(128) bf16 d_cih[(size_t)Bc*Pp*512];
__device__ __align__(128) bf16 d_cil[(size_t)Bc*Pp*512];
__device__ __align__(128) bf16 d_WtH[589824];
__device__ __align__(128) bf16 d_WtL[589824];

// ---------------- helpers -----------------------------------------------------
__device__ __forceinline__ void split_store(bf16* H, bf16* L, size_t idx, float v) {
    bf16 h = __float2bfloat16(v);
    H[idx] = h;
    L[idx] = __float2bfloat16(v - __bfloat162float(h));
}
__device__ __forceinline__ uint32_t bfpack(float a, float b) {
    __nv_bfloat162 p = __floats2bfloat162_rn(a, b);
    return *(uint32_t*)&p;
}
__device__ __forceinline__ uint32_t smem_u32(const void* p) {
    uint32_t a;
    asm("{ .reg .u64 t; cvta.to.shared.u64 t, %1; cvt.u32.u64 %0, t; }" : "=r"(a) : "l"(p));
    return a;
}
__device__ __forceinline__ void cpa16(uint32_t d, const void* s) {
    asm volatile("cp.async.cg.shared.global [%0], [%1], 16;" :: "r"(d), "l"(s));
}
#define CP_COMMIT() asm volatile("cp.async.commit_group;" ::: "memory")
#define CP_WAIT(n)  asm volatile("cp.async.wait_group %0;" :: "n"(n) : "memory")

// ---------------- K0: all weights transpose + split + bias concat -------------
struct WtTab {
    const float* W[7];
    int K[7], N[7];
    int off[7];
    int blkStart[8];
    const float *b0, *b1, *b2;
};
__global__ void k_wt_all(WtTab tb, bf16* __restrict__ oh, bf16* __restrict__ ol,
                         float* __restrict__ bcat) {
    int bid = blockIdx.x;
    if (bid >= tb.blkStart[7]) {
        int t = (bid - tb.blkStart[7]) * 256 + threadIdx.x;
        const float* src = (t < 256) ? tb.b0 : ((t < 512) ? tb.b1 : tb.b2);
        bcat[t] = src[t & 255];
        return;
    }
    int mi = 0;
    while (bid >= tb.blkStart[mi + 1]) mi++;
    int id = (bid - tb.blkStart[mi]) * 256 + threadIdx.x;
    int K = tb.K[mi], N = tb.N[mi];
    if (id >= K * N) return;
    int n = id / K, k = id % K;
    float w = tb.W[mi][(size_t)k * N + n];
    split_store(oh + tb.off[mi], ol + tb.off[mi], id, w);
}

// ---------------- K1: fused prep (zero agg | ax | eg | efp) -------------------
__global__ void k_prep(const float* __restrict__ nf, const float* __restrict__ adj,
                       const int* __restrict__ nob, const float* __restrict__ ef,
                       const int* __restrict__ ei, const int* __restrict__ ned,
                       const int* __restrict__ op) {
    int bid = blockIdx.x, t = threadIdx.x;         // 128 threads
    __shared__ int idxs[Nn_];
    __shared__ int cnt;
    if (bid < 2048) {                              // ---- ax ----
        int b = bid >> 7, i = bid & 127;
        int no = nob[b];
        size_t rbase = ((size_t)b * Nn_ + i) * DN_;
        if (t == 0) cnt = 0;
        __syncthreads();
        if (i >= no) {
            for (int c = t; c < DN_; c += 128) {
                d_Xh[rbase + c] = __float2bfloat16(0.f);  d_Xl[rbase + c] = __float2bfloat16(0.f);
                d_T2h[rbase + c] = __float2bfloat16(0.f); d_T2l[rbase + c] = __float2bfloat16(0.f);
            }
            return;
        }
        const float* arow = adj + ((size_t)b * Nn_ + i) * Nn_;
        const float* nfb  = nf  + (size_t)b * Nn_ * DN_;
        if (t < no && arow[t] != 0.f) { int p = atomicAdd(&cnt, 1); idxs[p] = t; }
        __syncthreads();
        int nn = cnt;
        for (int c = t; c < DN_; c += 128) {
            float x = nfb[(size_t)i * DN_ + c];
            float acc = x;
            for (int e = 0; e < nn; e++) acc += nfb[(size_t)idxs[e] * DN_ + c];
            split_store(d_Xh,  d_Xl,  rbase + c, x);
            split_store(d_T2h, d_T2l, rbase + c, acc);
        }
    } else if (bid < 18432) {                      // ---- eg ----
        int id = bid - 2048;
        int b = id >> 10, m = id & 1023;
        float2* dst = (float2*)(d_Eg + ((size_t)b * Mm + m) * DE_);
        if (m >= ned[b]) { dst[t] = make_float2(0.f, 0.f); return; }
        int s = ei[(b * 2 + 0) * Mm + m];
        int d = ei[(b * 2 + 1) * Mm + m];
        dst[t] = ((const float2*)(ef + (((size_t)b * Nn_ + s) * Nn_ + d) * DE_))[t];
    } else if (bid < 26624) {                      // ---- efp ----
        int id = bid - 18432;
        int b = id >> 9, p = id & 511;
        int p0 = op[((size_t)b * Pp + p) * 2 + 0];
        int p1 = op[((size_t)b * Pp + p) * 2 + 1];
        float2 v = ((const float2*)(ef + (((size_t)b * Nn_ + p0) * Nn_ + p1) * DE_))[t];
        size_t base = ((size_t)b * Pp + p) * DE_ + t * 2;
        split_store(d_efph, d_efpl, base + 0, v.x);
        split_store(d_efph, d_efpl, base + 1, v.y);
    } else {                                       // ---- zero agg ----
        d_agg[(size_t)(bid - 26624) * 128 + t] = 0.f;
    }
}

// ---------------- K2: T1 = L @ Eg  (sparse, unroll-4 accum) -------------------
__global__ void k_lspmm(const float* __restrict__ ladj, const int* __restrict__ ned) {
    int b = blockIdx.y, i = blockIdx.x, t = threadIdx.x;   // 256 threads
    int ne = ned[b];
    size_t rbase = ((size_t)b * Mm + i) * DE_;
    __shared__ int idxs[Mm];
    __shared__ int cnt;
    if (t == 0) cnt = 0;
    __syncthreads();
    if (i >= ne) {
        d_T1h[rbase + t] = __float2bfloat16(0.f);
        d_T1l[rbase + t] = __float2bfloat16(0.f);
        return;
    }
    const float4* lrow4 = (const float4*)(ladj + ((size_t)b * Mm + i) * Mm);
    float4 v = lrow4[t];
    int base = t * 4;
    if (base     < ne && v.x != 0.f) idxs[atomicAdd(&cnt, 1)] = base;
    if (base + 1 < ne && v.y != 0.f) idxs[atomicAdd(&cnt, 1)] = base + 1;
    if (base + 2 < ne && v.z != 0.f) idxs[atomicAdd(&cnt, 1)] = base + 2;
    if (base + 3 < ne && v.w != 0.f) idxs[atomicAdd(&cnt, 1)] = base + 3;
    __syncthreads();
    int nn = cnt;
    const float* Egb = d_Eg + (size_t)b * Mm * DE_;
    float a0 = Egb[(size_t)i * DE_ + t], a1 = 0.f, a2 = 0.f, a3 = 0.f;
    int e = 0;
    for (; e + 4 <= nn; e += 4) {
        a0 += Egb[(size_t)idxs[e]     * DE_ + t];
        a1 += Egb[(size_t)idxs[e + 1] * DE_ + t];
        a2 += Egb[(size_t)idxs[e + 2] * DE_ + t];
        a3 += Egb[(size_t)idxs[e + 3] * DE_ + t];
    }
    for (; e < nn; e++) a0 += Egb[(size_t)idxs[e] * DE_ + t];
    split_store(d_T1h, d_T1l, rbase + t, (a0 + a1) + (a2 + a3));
}

// ---------------- multi-segment wmma GEMM (cp.async double-buffered) ----------
#define F_RELU 1
#define F_BIAS 2
#define F_SPLIT 4
#define F_SCATTER 8
#define LDS_T 40
#define LDS_S 132
#define STAGE_B 40960

struct Seg {
    const bf16 *Ah, *Al, *Bh, *Bl;
    const float* bias;
    float* Cf;
    bf16 *Ch, *Cl;
    const int* ei;
    float* agg;
    int K, ldc, colOff, flags, nColBlk, blkEnd;
};
struct SegTable { Seg s[4]; int nseg; };

__global__ void __launch_bounds__(256, 2)
wgemm_multi(SegTable tab) {
    extern __shared__ char smem[];
    int bid = blockIdx.x, t = threadIdx.x, wid = t >> 5;
    int si = 0;
    while (si + 1 < tab.nseg && bid >= tab.s[si].blkEnd) si++;
    const Seg sg = tab.s[si];
    int blk0 = (si == 0) ? 0 : tab.s[si - 1].blkEnd;
    int local = bid - blk0;
    int rb = (local / sg.nColBlk) * 128;
    int cb = (local % sg.nColBlk) * 128;
    const int K = sg.K;
    const int nch = K >> 5;

    const uint32_t sm = smem_u32(smem);
    const int row = t >> 1, part = t & 1;

    wmma::fragment<wmma::accumulator, 16, 16, 16, float> acc[2][4];
    #pragma unroll
    for (int m = 0; m < 2; m++)
        #pragma unroll
        for (int n = 0; n < 4; n++) wmma::fill_fragment(acc[m][n], 0.0f);
    int wm = wid & 3, wn = wid >> 2;

    auto load_chunk = [&](int kc, int buf) {
        const bf16* gsrc[4] = {sg.Ah, sg.Al, sg.Bh, sg.Bl};
        int rbase[4] = {rb, rb, cb, cb};
        #pragma unroll
        for (int tile = 0; tile < 4; tile++) {
            const char* src = (const char*)(gsrc[tile] + (size_t)(rbase[tile] + row) * K + kc * 32) + part * 32;
            uint32_t dst = sm + buf * STAGE_B + tile * 10240 + row * 80 + part * 32;
            cpa16(dst, src);
            cpa16(dst + 16, src + 16);
        }
    };

    load_chunk(0, 0);
    CP_COMMIT();
    for (int kc = 0; kc < nch; kc++) {
        if (kc + 1 < nch) { load_chunk(kc + 1, (kc + 1) & 1); CP_COMMIT(); CP_WAIT(1); }
        else              { CP_WAIT(0); }
        __syncthreads();
        const bf16* Ahs = (const bf16*)(smem + (kc & 1) * STAGE_B);
        const bf16* Als = Ahs + 5120;
        const bf16* Bhs = Ahs + 10240;
        const bf16* Bls = Ahs + 15360;
        #pragma unroll
        for (int kk = 0; kk < 2; kk++) {
            wmma::fragment<wmma::matrix_a, 16, 16, 16, bf16, wmma::row_major> fah[2], fal[2];
            #pragma unroll
            for (int m = 0; m < 2; m++) {
                wmma::load_matrix_sync(fah[m], Ahs + (wm * 32 + m * 16) * LDS_T + kk * 16, LDS_T);
                wmma::load_matrix_sync(fal[m], Als + (wm * 32 + m * 16) * LDS_T + kk * 16, LDS_T);
            }
            #pragma unroll
            for (int n = 0; n < 4; n++) {
                wmma::fragment<wmma::matrix_b, 16, 16, 16, bf16, wmma::col_major> fbh, fbl;
                wmma::load_matrix_sync(fbh, Bhs + (wn * 64 + n * 16) * LDS_T + kk * 16, LDS_T);
                wmma::load_matrix_sync(fbl, Bls + (wn * 64 + n * 16) * LDS_T + kk * 16, LDS_T);
                #pragma unroll
                for (int m = 0; m < 2; m++) {
                    wmma::mma_sync(acc[m][n], fah[m], fbh, acc[m][n]);
                    wmma::mma_sync(acc[m][n], fah[m], fbl, acc[m][n]);
                    wmma::mma_sync(acc[m][n], fal[m], fbh, acc[m][n]);
                }
            }
        }
        __syncthreads();
    }

    // ---- epilogue ----
    float* stage = (float*)smem;
    #pragma unroll
    for (int m = 0; m < 2; m++)
        #pragma unroll
        for (int n = 0; n < 4; n++)
            wmma::store_matrix_sync(stage + (wm * 32 + m * 16) * LDS_S + wn * 64 + n * 16,
                                    acc[m][n], LDS_S, wmma::mem_row_major);
    __syncthreads();
    int r = t >> 1, ch = (t & 1) * 64;
    const float* srow = stage + r * LDS_S + ch;
    if (sg.flags & F_SCATTER) {
        int m = rb + r, b = m >> 10, mm = m & 1023;
        int s = sg.ei[(b * 2) * Mm + mm];
        float* dst = sg.agg + ((size_t)(b * Nn_ + s)) * WE_ + ch;
        for (int q = 0; q < 64; q++) {
            float v = fmaxf(srow[q], 0.f);
            if (v != 0.f) atomicAdd(dst + q, v);
        }
    } else if (sg.flags & F_SPLIT) {
        size_t base = (size_t)(rb + r) * sg.ldc + sg.colOff + cb + ch;
        uint32_t* CH = (uint32_t*)(sg.Ch + base);
        uint32_t* CL = (uint32_t*)(sg.Cl + base);
        #pragma unroll 8
        for (int q = 0; q < 32; q++) {
            float v0 = srow[2 * q], v1 = srow[2 * q + 1];
            if (sg.flags & F_RELU) { v0 = fmaxf(v0, 0.f); v1 = fmaxf(v1, 0.f); }
            bf16 h0 = __float2bfloat16(v0), h1 = __float2bfloat16(v1);
            float l0 = v0 - __bfloat162float(h0), l1 = v1 - __bfloat162float(h1);
            CH[q] = (uint32_t)__bfloat16_as_ushort(h0) | ((uint32_t)__bfloat16_as_ushort(h1) << 16);
            CL[q] = bfpack(l0, l1);
        }
    } else {
        float* crow = sg.Cf + (size_t)(rb + r) * sg.ldc + cb + ch;
        #pragma unroll 4
        for (int q = 0; q < 16; q++) {
            float4 v = *(const float4*)(srow + q * 4);
            if (sg.flags & F_BIAS) {
                int gc = cb + ch + q * 4;
                v.x += sg.bias[gc + 0]; v.y += sg.bias[gc + 1];
                v.z += sg.bias[gc + 2]; v.w += sg.bias[gc + 3];
            }
            if (sg.flags & F_RELU) {
                v.x = fmaxf(v.x, 0.f); v.y = fmaxf(v.y, 0.f);
                v.z = fmaxf(v.z, 0.f); v.w = fmaxf(v.w, 0.f);
            }
            *(float4*)(crow + q * 4) = v;
        }
    }
}

// ---------------- K5: assemble ci columns [0,384) -> bf16 splits --------------
__global__ void k_ci(const int* __restrict__ op, const int* __restrict__ nob) {
    int b = blockIdx.y, p = blockIdx.x, t = threadIdx.x;   // 128 threads
    int p0 = op[((size_t)b * Pp + p) * 2 + 0];
    int p1 = op[((size_t)b * Pp + p) * 2 + 1];
    int no = nob[b];
    float m0 = (p0 < no) ? 1.f : 0.f;
    float m1 = (p1 < no) ? 1.f : 0.f;
    size_t base = ((size_t)b * Pp + p) * 512;
    const float* h0 = d_h   + ((size_t)b * Nn_ + p0) * WN_;
    const float* h1 = d_h   + ((size_t)b * Nn_ + p1) * WN_;
    const float* a0 = d_agg + ((size_t)b * Nn_ + p0) * WE_;
    const float* a1 = d_agg + ((size_t)b * Nn_ + p1) * WE_;
    const float* x0 = d_Xp  + ((size_t)b * Nn_ + p0) * WN_;
    const float* x1 = d_Xp  + ((size_t)b * Nn_ + p1) * WN_;
    split_store(d_cih, d_cil, base + t,       h0[t] + h1[t]);
    split_store(d_cih, d_cil, base + 128 + t, a0[t] * m0 + a1[t] * m1);
    split_store(d_cih, d_cil, base + 256 + t, fmaxf(x0[t] + x1[t], 0.f));
}

// ---------------- K7: MLP layer 2, three heads fused --------------------------
__global__ void k_head(const float* __restrict__ Wl, const float* __restrict__ bl,
                       const float* __restrict__ Wc, const float* __restrict__ bc,
                       const float* __restrict__ Wm, const float* __restrict__ bm,
                       float* __restrict__ out) {
    int r = blockIdx.x;
    int t = threadIdx.x;        // 256
    __shared__ float hs[768];
    for (int c = t; c < 768; c += 256) hs[c] = d_hid[(size_t)r * 768 + c];
    __syncthreads();
    int o = t >> 3, l = t & 7;
    const float* W; const float* bb; const float* hrow; int od, oc; float* dst;
    if (o < 9)       { W = Wl; bb = bl; hrow = hs;       od = 9;  oc = o;      dst = out +          (size_t)r * 9  + oc; }
    else if (o < 15) { W = Wc; bb = bc; hrow = hs + 256; od = 6;  oc = o - 9;  dst = out + 73728  + (size_t)r * 6  + oc; }
    else             { W = Wm; bb = bm; hrow = hs + 512; od = 17; oc = o - 15; dst = out + 122880 + (size_t)r * 17 + oc; }
    float s = 0.f;
    for (int k = l; k < 256; k += 8) s += hrow[k] * W[(size_t)k * od + oc];
    #pragma unroll
    for (int off = 4; off; off >>= 1) s += __shfl_down_sync(0xffffffffu, s, off, 8);
    if (l == 0) *dst = s + bb[oc];
}

// ---------------- launch -----------------------------------------------------
extern "C" void kernel_launch(void* const* d_in, const int* in_sizes, int n_in,
                              void* d_out, int out_size) {
    const float* nf   = (const float*)d_in[0];
    const float* ef   = (const float*)d_in[1];
    const float* adj  = (const float*)d_in[2];
    const float* ladj = (const float*)d_in[3];
    const int*   ei   = (const int*)  d_in[4];
    const int*   op   = (const int*)  d_in[5];
    const int*   nob  = (const int*)  d_in[6];
    const int*   ned  = (const int*)  d_in[7];
    const float* Wn   = (const float*)d_in[8];
    const float* We   = (const float*)d_in[9];
    const float* Wn2  = (const float*)d_in[10];
    const float* We2  = (const float*)d_in[11];
    const float* scrW1= (const float*)d_in[12];
    const float* scrb1= (const float*)d_in[13];
    const float* scrW2= (const float*)d_in[14];
    const float* scrb2= (const float*)d_in[15];
    const float* lrW1 = (const float*)d_in[16];
    const float* lrb1 = (const float*)d_in[17];
    const float* lrW2 = (const float*)d_in[18];
    const float* lrb2 = (const float*)d_in[19];
    const float* mrW1 = (const float*)d_in[20];
    const float* mrb1 = (const float*)d_in[21];
    const float* mrW2 = (const float*)d_in[22];
    const float* mrb2 = (const float*)d_in[23];
    float* out = (float*)d_out;

    bf16 *pWtH, *pWtL, *pT1h, *pT1l, *pT2h, *pT2l, *pXh, *pXl, *pEfph, *pEfpl, *pCih, *pCil;
    float *pH, *pXp, *pAgg, *pHid, *pB1;
    cudaGetSymbolAddress((void**)&pWtH, d_WtH);
    cudaGetSymbolAddress((void**)&pWtL, d_WtL);
    cudaGetSymbolAddress((void**)&pT1h, d_T1h);
    cudaGetSymbolAddress((void**)&pT1l, d_T1l);
    cudaGetSymbolAddress((void**)&pT2h, d_T2h);
    cudaGetSymbolAddress((void**)&pT2l, d_T2l);
    cudaGetSymbolAddress((void**)&pXh,  d_Xh);
    cudaGetSymbolAddress((void**)&pXl,  d_Xl);
    cudaGetSymbolAddress((void**)&pEfph,d_efph);
    cudaGetSymbolAddress((void**)&pEfpl,d_efpl);
    cudaGetSymbolAddress((void**)&pCih, d_cih);
    cudaGetSymbolAddress((void**)&pCil, d_cil);
    cudaGetSymbolAddress((void**)&pH,   d_h);
    cudaGetSymbolAddress((void**)&pXp,  d_Xp);
    cudaGetSymbolAddress((void**)&pAgg, d_agg);
    cudaGetSymbolAddress((void**)&pHid, d_hid);
    cudaGetSymbolAddress((void**)&pB1,  d_b1cat);

    const int SMEM_BYTES = 2 * STAGE_B;   // 81920
    cudaFuncSetAttribute(wgemm_multi, cudaFuncAttributeMaxDynamicSharedMemorySize, SMEM_BYTES);

    // ---- K0: weights prep ----
    const int oWe = 0, oWn = 32768, oWn2 = 98304, oWe2 = 163840, oMlp = 196608;
    WtTab wt;
    const float* Ws[7] = {We, Wn, Wn2, We2, lrW1, scrW1, mrW1};
    int Ks[7] = {256, 512, 512, 256, 512, 512, 512};
    int Ns[7] = {128, 128, 128, 128, 256, 256, 256};
    int offs[7] = {oWe, oWn, oWn2, oWe2, oMlp, oMlp + 131072, oMlp + 262144};
    int bs = 0;
    for (int i = 0; i < 7; i++) {
        wt.W[i] = Ws[i]; wt.K[i] = Ks[i]; wt.N[i] = Ns[i]; wt.off[i] = offs[i];
        wt.blkStart[i] = bs;
        bs += (Ks[i] * Ns[i]) / 256;
    }
    wt.blkStart[7] = bs;
    wt.b0 = lrb1; wt.b1 = scrb1; wt.b2 = mrb1;
    k_wt_all<<<bs + 3, 256>>>(wt, pWtH, pWtL, pB1);

    // ---- K1: fused prep ----
    k_prep<<<28672, 128>>>(nf, adj, nob, ef, ei, ned, op);
    // ---- K2: line-graph SpMM ----
    k_lspmm<<<dim3(Mm, Bc), 256>>>(ladj, ned);

    // ---- K3: fused GEMM wave: g(scatter) + h + Xp + Q(split) ----
    SegTable t4 = {};
    t4.nseg = 4;
    t4.s[0] = {pT1h, pT1l, pWtH + oWe, pWtL + oWe, nullptr, nullptr, nullptr, nullptr,
               ei, pAgg, 256, 0, 0, F_RELU | F_SCATTER, 1, 128};
    t4.s[1] = {pT2h, pT2l, pWtH + oWn, pWtL + oWn, nullptr, pH, nullptr, nullptr,
               nullptr, nullptr, 512, 128, 0, F_RELU, 1, 144};
    t4.s[2] = {pXh, pXl, pWtH + oWn2, pWtL + oWn2, nullptr, pXp, nullptr, nullptr,
               nullptr, nullptr, 512, 128, 0, 0, 1, 160};
    t4.s[3] = {pEfph, pEfpl, pWtH + oWe2, pWtL + oWe2, nullptr, nullptr, pCih, pCil,
               nullptr, nullptr, 256, 512, 384, F_RELU | F_SPLIT, 1, 224};
    wgemm_multi<<<224, 256, SMEM_BYTES>>>(t4);

    // ---- K4: ci assembly (cols 0..383) ----
    k_ci<<<dim3(Pp, Bc), 128>>>(op, nob);

    // ---- K5: MLP layer 1 fused heads [8192 x 768 x 512] ----
    SegTable t1 = {};
    t1.nseg = 1;
    t1.s[0] = {pCih, pCil, pWtH + oMlp, pWtL + oMlp, pB1, pHid, nullptr, nullptr,
               nullptr, nullptr, 512, 768, 0, F_RELU | F_BIAS, 6, 384};
    wgemm_multi<<<384, 256, SMEM_BYTES>>>(t1);

    // ---- K6: MLP layer 2 -> out ----
    k_head<<<Bc*Pp, 256>>>(lrW2, lrb2, scrW2, scrb2, mrW2, mrb2, out);
}